// round 15
// baseline (speedup 1.0000x reference)
#include <cuda_runtime.h>
#include <cuda_fp16.h>
#include <math.h>
#include <stdint.h>

// Problem constants
static const int B_ = 4;
static const int T_ = 1024;
static const int E_ = 2048;
static const int H_ = 32;
static const int D_ = 64;
static const int BT_ = B_ * T_;      // 4096
static const int BH_ = B_ * H_;      // 128

// Scratch (device globals; no allocation allowed)
__device__ float g_q[BH_ * T_ * D_];    // [B,H,T,D] fp32 projections
__device__ float g_k[BH_ * T_ * D_];
__device__ float g_v[BH_ * T_ * D_];    // after v_quant: integer (q-z) values
__device__ float g_s[BH_ * D_];         // SmoothK per-channel scale
__device__ float g_vs[BH_ * D_];        // V quant scale per (bh,d)
__device__ char g_hsi[BT_ * E_ * 4];    // hs image (hi/lo fp16 fragment layout)
__device__ char g_wi[4 * E_ * E_ * 4];  // wq,wk,wv,wo images
__device__ char g_ctxi[BT_ * E_ * 4];   // ctx image (written by attention)
__device__ char g_qi[BH_ * T_ * 256];   // quantized Q image (256B per row)
__device__ char g_ki[BH_ * T_ * 256];   // quantized K image

// ============================================================================
// common helpers
// ============================================================================
__device__ __forceinline__ void mma_f16(float* c, uint32_t a0, uint32_t a1,
                                        uint32_t a2, uint32_t a3,
                                        uint32_t b0, uint32_t b1) {
    asm volatile(
        "mma.sync.aligned.m16n8k16.row.col.f32.f16.f16.f32 "
        "{%0,%1,%2,%3}, {%4,%5,%6,%7}, {%8,%9}, {%0,%1,%2,%3};"
        : "+f"(c[0]), "+f"(c[1]), "+f"(c[2]), "+f"(c[3])
        : "r"(a0), "r"(a1), "r"(a2), "r"(a3), "r"(b0), "r"(b1));
}

// split two floats -> packed hi half2 and lo half2 (lo pre-scaled by 2048)
__device__ __forceinline__ void h2split(float x, float y, uint32_t& h,
                                        uint32_t& l) {
    __half2 hh = __floats2half2_rn(x, y);
    float2 hf = __half22float2(hh);
    __half2 ll = __floats2half2_rn((x - hf.x) * 2048.f, (y - hf.y) * 2048.f);
    h = *(uint32_t*)&hh;
    l = *(uint32_t*)&ll;
}

__device__ __forceinline__ uint32_t h2pack(float x, float y) {
    __half2 hh = __floats2half2_rn(x, y);
    return *(uint32_t*)&hh;
}

__device__ __forceinline__ void ldsm_x4_t(uint32_t& r0, uint32_t& r1,
                                          uint32_t& r2, uint32_t& r3,
                                          uint32_t addr) {
    asm volatile(
        "ldmatrix.sync.aligned.m8n8.x4.trans.shared.b16 {%0,%1,%2,%3}, [%4];"
        : "=r"(r0), "=r"(r1), "=r"(r2), "=r"(r3) : "r"(addr));
}

__device__ __forceinline__ uint32_t smem_u32(const void* p) {
    uint32_t a;
    asm("{ .reg .u64 t; cvta.to.shared.u64 t, %1; cvt.u32.u64 %0, t; }"
        : "=r"(a) : "l"(p));
    return a;
}

// ============================================================================
// split kernel: fp32 row-major -> hi/lo fp16 fragment-image layout.
// ============================================================================
__global__ __launch_bounds__(256) void split_all(
    const float* __restrict__ hs,
    const float* __restrict__ w0, const float* __restrict__ w1,
    const float* __restrict__ w2, const float* __restrict__ w3,
    char* __restrict__ hsi, char* __restrict__ wi)
{
    const int idx = blockIdx.x * 256 + threadIdx.x;
    const int row = idx >> 9;
    const int f = idx & 511;

    const float* src;
    char* dst;
    if (row < BT_) {
        src = hs + (size_t)row * E_;
        dst = hsi + (size_t)row * 8192;
    } else {
        const int r2 = row - BT_;
        const int w = r2 >> 11;
        const int wr = r2 & 2047;
        src = ((w == 0) ? w0 : (w == 1) ? w1 : (w == 2) ? w2 : w3) +
              (size_t)wr * E_;
        dst = wi + ((size_t)w * E_ + wr) * 8192;
    }

    float4 v = *(const float4*)(src + f * 4);
    const int chunk = f >> 3;
    const int k4 = f & 7;
    const int ks_f = k4 >> 2;
    const int p0 = (2 * k4) & 7;
    const int p1 = p0 + 1;
    const int off0 = ks_f * 64 + (p0 & 3) * 16 + ((p0 >> 2) & 1) * 4;
    const int off1 = ks_f * 64 + (p1 & 3) * 16 + ((p1 >> 2) & 1) * 4;

    uint32_t h0, l0, h1, l1;
    h2split(v.x, v.y, h0, l0);
    h2split(v.z, v.w, h1, l1);
    char* d = dst + chunk * 128;
    *(uint32_t*)(d + off0) = h0;
    *(uint32_t*)(d + off1) = h1;
    *(uint32_t*)(d + off0 + 8) = l0;
    *(uint32_t*)(d + off1 + 8) = l1;
}

// ============================================================================
// fp16 two-term-split GEMM via mma.sync.m16n8k16 from pre-split images.
// ============================================================================
static const int NCH_ = 64;
static const int RSB_ = 192;
static const int OPBYTES_ = 128 * RSB_;
static const int GEMM_SMEM_ = 4 * OPBYTES_;

template <int MODE>
__device__ __forceinline__ void gemm_body(
    const uint4* __restrict__ Aimg, const uint4* __restrict__ Wimg,
    const float* __restrict__ bias, float* __restrict__ C, float scale,
    int bm, int bn, char* smem)
{
    const int tid = threadIdx.x;
    const int wid = tid >> 5;
    const int lane = tid & 31;

    const int wm = (wid & 1) * 64;
    const int wn = (wid >> 1) * 32;
    const int gq = lane >> 2;
    const int tg = lane & 3;

    const int row0 = tid >> 3;
    const int grp = tid & 7;
    size_t goffA[4], goffB[4];
    int stsOff[4];
#pragma unroll
    for (int j = 0; j < 4; j++) {
        const int r = row0 + 32 * j;
        stsOff[j] = r * RSB_ + grp * 16;
        goffA[j] = (size_t)(bm + r) * 512 + grp;
        goffB[j] = (size_t)(bn + r) * 512 + grp;
    }

    float accM[4][4][4], accC[4][4][4];
#pragma unroll
    for (int mt = 0; mt < 4; mt++)
#pragma unroll
        for (int nt = 0; nt < 4; nt++)
#pragma unroll
            for (int x = 0; x < 4; x++) {
                accM[mt][nt][x] = 0.f;
                accC[mt][nt][x] = 0.f;
            }

    {
        char* sA = smem;
        char* sB = smem + 2 * OPBYTES_;
#pragma unroll
        for (int j = 0; j < 4; j++) {
            *(uint4*)(sA + stsOff[j]) = Aimg[goffA[j]];
            *(uint4*)(sB + stsOff[j]) = Wimg[goffB[j]];
        }
    }
    __syncthreads();

    for (int c = 0; c < NCH_; c++) {
        uint4 pa[4], pb[4];
        const bool pf = (c + 1 < NCH_);
        if (pf) {
            const int co = (c + 1) * 8;
#pragma unroll
            for (int j = 0; j < 4; j++) {
                pa[j] = Aimg[goffA[j] + co];
                pb[j] = Wimg[goffB[j] + co];
            }
        }

        const char* sA = smem + (c & 1) * OPBYTES_;
        const char* sB = smem + 2 * OPBYTES_ + (c & 1) * OPBYTES_;
#pragma unroll
        for (int ks = 0; ks < 2; ks++) {
            uint4 bf[4];
#pragma unroll
            for (int nt = 0; nt < 4; nt++)
                bf[nt] = *(const uint4*)(sB + (wn + nt * 8 + gq) * RSB_ +
                                         ks * 64 + tg * 16);
#pragma unroll
            for (int mt = 0; mt < 4; mt++) {
                const char* ra =
                    sA + (wm + mt * 16 + gq) * RSB_ + ks * 64 + tg * 16;
                uint4 t = *(const uint4*)(ra);
                uint4 u = *(const uint4*)(ra + 8 * RSB_);
#pragma unroll
                for (int nt = 0; nt < 4; nt++) {
                    mma_f16(accM[mt][nt], t.x, u.x, t.y, u.y, bf[nt].x, bf[nt].y);
                    mma_f16(accC[mt][nt], t.z, u.z, t.w, u.w, bf[nt].x, bf[nt].y);
                    mma_f16(accC[mt][nt], t.x, u.x, t.y, u.y, bf[nt].z, bf[nt].w);
                }
            }
        }

        if (pf) {
            char* dA = smem + ((c + 1) & 1) * OPBYTES_;
            char* dB = smem + 2 * OPBYTES_ + ((c + 1) & 1) * OPBYTES_;
#pragma unroll
            for (int j = 0; j < 4; j++) {
                *(uint4*)(dA + stsOff[j]) = pa[j];
                *(uint4*)(dB + stsOff[j]) = pb[j];
            }
        }
        __syncthreads();
    }

    const float inv2048 = 1.0f / 2048.0f;
#pragma unroll
    for (int mt = 0; mt < 4; mt++) {
#pragma unroll
        for (int nt = 0; nt < 4; nt++) {
            const int n0 = bn + wn + nt * 8 + tg * 2;
            const float b0 = bias[n0], b1 = bias[n0 + 1];
#pragma unroll
            for (int half = 0; half < 2; half++) {
                const int m = bm + wm + mt * 16 + gq + half * 8;
                float2 v;
                v.x = (accM[mt][nt][half * 2 + 0] +
                       accC[mt][nt][half * 2 + 0] * inv2048 + b0) * scale;
                v.y = (accM[mt][nt][half * 2 + 1] +
                       accC[mt][nt][half * 2 + 1] * inv2048 + b1) * scale;
                if (MODE == 0) {
                    *(float2*)(C + (size_t)m * E_ + n0) = v;
                } else {
                    const int b = m >> 10, t = m & 1023;
                    const int h = n0 >> 6, d0 = n0 & 63;
                    *(float2*)(C + (((size_t)(b * H_ + h)) * T_ + t) * D_ + d0) = v;
                }
            }
        }
    }
}

// merged QKV projection: grid (48, 32); bx>>4 selects Q/K/V
__global__ __launch_bounds__(256, 1) void qkv_gemm(
    const uint4* __restrict__ hsi, const uint4* __restrict__ wi,
    const float* __restrict__ bq, const float* __restrict__ bk,
    const float* __restrict__ bv,
    float* __restrict__ q, float* __restrict__ k, float* __restrict__ v)
{
    extern __shared__ char smem[];
    const int which = blockIdx.x >> 4;
    const int bn = (blockIdx.x & 15) * 128;
    const int bm = blockIdx.y * 128;
    const size_t WPITCH = (size_t)E_ * E_ * 4 / 16;
    const uint4* W = wi + (size_t)which * WPITCH;
    const float* bias = (which == 0) ? bq : (which == 1) ? bk : bv;
    float* C = (which == 0) ? q : (which == 1) ? k : v;
    const float scale = (which == 0) ? 0.125f : 1.0f;
    gemm_body<1>(hsi, W, bias, C, scale, bm, bn, smem);
}

// out projection
__global__ __launch_bounds__(256, 1) void out_gemm(
    const uint4* __restrict__ ctxi, const uint4* __restrict__ wi,
    const float* __restrict__ bias, float* __restrict__ C)
{
    extern __shared__ char smem[];
    gemm_body<0>(ctxi, wi, bias, C, 1.0f, blockIdx.y * 128, blockIdx.x * 128,
                 smem);
}

// ---------------------------------------------------------------------------
// SmoothK per-channel abs-max over tokens
// ---------------------------------------------------------------------------
__global__ __launch_bounds__(256) void smooth_absmax(
    const float* __restrict__ Kin, float* __restrict__ S)
{
    const int bh = blockIdx.x;
    const int dt = threadIdx.x >> 6;
    const int d = threadIdx.x & 63;
    const float* p = Kin + (size_t)bh * T_ * D_ + d;
    float m = 0.f;
    for (int t = dt; t < T_; t += 4) m = fmaxf(m, fabsf(p[(size_t)t * D_]));
    __shared__ float sm[4][64];
    sm[dt][d] = m;
    __syncthreads();
    if (dt == 0) {
        float r = fmaxf(fmaxf(sm[0][d], sm[1][d]), fmaxf(sm[2][d], sm[3][d]));
        S[bh * 64 + d] = fmaxf(r, 1e-5f);
    }
}

// ---------------------------------------------------------------------------
// Per-row asymmetric fake quant; writes the hi/lo fp16 IMAGE (256B per row).
// ---------------------------------------------------------------------------
template <bool SMOOTH>
__global__ __launch_bounds__(256) void row_quant_img(
    const float* __restrict__ X, const float* __restrict__ S,
    char* __restrict__ IMG)
{
    const int row = blockIdx.x * 8 + (threadIdx.x >> 5);
    const int lane = threadIdx.x & 31;
    const float* p = X + (size_t)row * 64;

    float s0 = 1.f, s1 = 1.f;
    if (SMOOTH) {
        const int bh = row >> 10;
        s0 = S[bh * 64 + lane];
        s1 = S[bh * 64 + lane + 32];
    }
    float x0 = p[lane] / s0;
    float x1 = p[lane + 32] / s1;

    float mx = fmaxf(fmaxf(x0, x1), 0.f);
    float mn = fminf(fminf(x0, x1), 0.f);
#pragma unroll
    for (int o = 16; o > 0; o >>= 1) {
        mx = fmaxf(mx, __shfl_xor_sync(0xffffffffu, mx, o));
        mn = fminf(mn, __shfl_xor_sync(0xffffffffu, mn, o));
    }
    float scale = (mx - mn) / 255.0f;
    if (scale <= 0.f) scale = 1.f;
    const float zero = rintf(-mn / scale);
    float q0 = fminf(fmaxf(rintf(x0 / scale) + zero, 0.f), 255.f);
    float q1 = fminf(fmaxf(rintf(x1 / scale) + zero, 0.f), 255.f);
    const float v0 = scale * (q0 - zero) * s0;
    const float v1 = scale * (q1 - zero) * s1;

    const float w0 = __shfl_xor_sync(0xffffffffu, v0, 1);
    const float w1 = __shfl_xor_sync(0xffffffffu, v1, 1);
    if ((lane & 1) == 0) {
        char* dst = IMG + (size_t)row * 256;
        const int ppA = lane >> 1;
        const int offA = (ppA >> 3) * 64 + (ppA & 3) * 16 + ((ppA >> 2) & 1) * 4;
        uint32_t h, l;
        h2split(v0, w0, h, l);
        *(uint32_t*)(dst + offA) = h;
        *(uint32_t*)(dst + offA + 8) = l;
        h2split(v1, w1, h, l);
        *(uint32_t*)(dst + 128 + offA) = h;
        *(uint32_t*)(dst + 128 + offA + 8) = l;
    }
}

// ---------------------------------------------------------------------------
// V fake quant along the token axis (integer levels + scale).
// ---------------------------------------------------------------------------
__global__ __launch_bounds__(256) void v_quant(float* __restrict__ V,
                                               float* __restrict__ VS)
{
    const int bh = blockIdx.x;
    const int dt = threadIdx.x >> 6;
    const int d = threadIdx.x & 63;
    float* p = V + (size_t)bh * T_ * D_ + d;

    float mx = 0.f, mn = 0.f;
    for (int t = dt; t < T_; t += 4) {
        float x = p[(size_t)t * D_];
        mx = fmaxf(mx, x);
        mn = fminf(mn, x);
    }
    __shared__ float smx[4][64], smn[4][64];
    smx[dt][d] = mx; smn[dt][d] = mn;
    __syncthreads();
    mx = fmaxf(fmaxf(smx[0][d], smx[1][d]), fmaxf(smx[2][d], smx[3][d]));
    mn = fminf(fminf(smn[0][d], smn[1][d]), fminf(smn[2][d], smn[3][d]));

    float scale = (mx - mn) / 255.0f;
    if (scale <= 0.f) scale = 1.f;
    const float zero = rintf(-mn / scale);
    if (dt == 0) VS[bh * 64 + d] = scale;
    for (int t = dt; t < T_; t += 4) {
        float x = p[(size_t)t * D_];
        float q = fminf(fmaxf(rintf(x / scale) + zero, 0.f), 255.f);
        p[(size_t)t * D_] = q - zero;
    }
}

// ============================================================================
// Tensor-core flash attention: Q/K from pre-quantized images (pure copies);
// V exact-integer fp16 (2-pass PV, scale at epilogue); writes ctx image.
// ============================================================================
static const int QKS_ = 320;
static const int VS_ = 144;
static const int SM_Q_ = 0;
static const int SM_K_ = 40960;
static const int SM_V_ = 81920;
static const int VSTG_ = 9216;
static const int ATTN_SMEM_ = SM_V_ + 2 * VSTG_;

__global__ __launch_bounds__(256, 1) void attn_mma(
    const uint4* __restrict__ Qi, const uint4* __restrict__ Ki,
    const float* __restrict__ Vb, const float* __restrict__ VS,
    char* __restrict__ ctxi)
{
    extern __shared__ char smem[];
    const uint32_t sb = smem_u32(smem);

    const int bh = blockIdx.y;
    const int qt = 7 - blockIdx.x;
    const int tid = threadIdx.x;
    const int wid = tid >> 5;
    const int lane = tid & 31;
    const int gq = lane >> 2;
    const int tg = lane & 3;
    const size_t base = (size_t)bh * T_;

    const int frow = tid >> 4;
    const int f4 = tid & 15;

    // ---- fill Q tile (pure copy) ----
#pragma unroll
    for (int j = 0; j < 8; j++) {
        const int r = frow + 16 * j;
        *(uint4*)(smem + SM_Q_ + r * QKS_ + f4 * 16) =
            Qi[(base + qt * 128 + r) * 16 + f4];
    }

    // ---- fill K/V ktile 0, stage 0 ----
#pragma unroll
    for (int j = 0; j < 4; j++) {
        const int r = frow + 16 * j;
        *(uint4*)(smem + SM_K_ + r * QKS_ + f4 * 16) = Ki[(base + r) * 16 + f4];
        float4 vv = *(const float4*)(Vb + (base + r) * D_ + f4 * 4);
        char* vh = smem + SM_V_ + r * VS_ + f4 * 8;
        *(uint2*)(vh) = make_uint2(h2pack(vv.x, vv.y), h2pack(vv.z, vv.w));
    }
    __syncthreads();

    float O[8][4];
#pragma unroll
    for (int nt = 0; nt < 8; nt++)
#pragma unroll
        for (int x = 0; x < 4; x++) O[nt][x] = 0.f;
    float m0 = -1e30f, m1 = -1e30f, l0s = 0.f, l1s = 0.f;

    const int r0g = qt * 128 + wid * 16 + gq;
    const int r1g = r0g + 8;
    const int nkt = 2 * (qt + 1);
    const float inv2048 = 1.0f / 2048.0f;
    const int vrow_off = (lane & 15) * VS_ + (lane >> 4) * 16;

    for (int kt = 0; kt < nkt; kt++) {
        const int stage = kt & 1;
        const uint32_t kbase = sb + SM_K_ + stage * 20480;
        const uint32_t vhbase = sb + SM_V_ + stage * VSTG_;

        uint4 pk[4];
        float4 pv[4];
        const bool pf = (kt + 1 < nkt);
        if (pf) {
            const size_t tok0 = (size_t)(kt + 1) * 64;
#pragma unroll
            for (int j = 0; j < 4; j++) {
                const size_t r = tok0 + frow + 16 * j;
                pk[j] = Ki[(base + r) * 16 + f4];
                pv[j] = *(const float4*)(Vb + (base + r) * D_ + f4 * 4);
            }
        }

        // ---- S = Q @ K^T (3-pass) ----
        float sm_[8][4], sc_[8][4];
#pragma unroll
        for (int nt = 0; nt < 8; nt++)
#pragma unroll
            for (int x = 0; x < 4; x++) { sm_[nt][x] = 0.f; sc_[nt][x] = 0.f; }

        const uint32_t qbase = sb + SM_Q_ + (wid * 16 + gq) * QKS_;
#pragma unroll
        for (int ks = 0; ks < 4; ks++) {
            uint4 tq, uq;
            asm volatile("ld.shared.v4.b32 {%0,%1,%2,%3}, [%4];"
                         : "=r"(tq.x), "=r"(tq.y), "=r"(tq.z), "=r"(tq.w)
                         : "r"(qbase + ks * 64 + tg * 16));
            asm volatile("ld.shared.v4.b32 {%0,%1,%2,%3}, [%4];"
                         : "=r"(uq.x), "=r"(uq.y), "=r"(uq.z), "=r"(uq.w)
                         : "r"(qbase + 8 * QKS_ + ks * 64 + tg * 16));
#pragma unroll
            for (int nt = 0; nt < 8; nt++) {
                uint4 bk;
                asm volatile("ld.shared.v4.b32 {%0,%1,%2,%3}, [%4];"
                             : "=r"(bk.x), "=r"(bk.y), "=r"(bk.z), "=r"(bk.w)
                             : "r"(kbase + (nt * 8 + gq) * QKS_ + ks * 64 + tg * 16));
                mma_f16(sm_[nt], tq.x, uq.x, tq.y, uq.y, bk.x, bk.y);
                mma_f16(sc_[nt], tq.z, uq.z, tq.w, uq.w, bk.x, bk.y);
                mma_f16(sc_[nt], tq.x, uq.x, tq.y, uq.y, bk.z, bk.w);
            }
        }

        float s[8][4];
        const bool maskit = (kt >= 2 * qt);
#pragma unroll
        for (int nt = 0; nt < 8; nt++)
#pragma unroll
            for (int x = 0; x < 4; x++) {
                float v = sm_[nt][x] + sc_[nt][x] * inv2048;
                if (maskit) {
                    const int col = kt * 64 + nt * 8 + tg * 2 + (x & 1);
                    const int row = (x < 2) ? r0g : r1g;
                    if (col > row) v = -INFINITY;
                }
                s[nt][x] = v;
            }

        // online softmax
        float rm0 = -1e30f, rm1 = -1e30f;
#pragma unroll
        for (int nt = 0; nt < 8; nt++) {
            rm0 = fmaxf(rm0, fmaxf(s[nt][0], s[nt][1]));
            rm1 = fmaxf(rm1, fmaxf(s[nt][2], s[nt][3]));
        }
        rm0 = fmaxf(rm0, __shfl_xor_sync(0xffffffffu, rm0, 1));
        rm0 = fmaxf(rm0, __shfl_xor_sync(0xffffffffu, rm0, 2));
        rm1 = fmaxf(rm1, __shfl_xor_sync(0xffffffffu, rm1, 1));
        rm1 = fmaxf(rm1, __shfl_xor_sync(0xffffffffu, rm1, 2));

        const float mn0 = fmaxf(m0, rm0);
        const float mn1 = fmaxf(m1, rm1);
        const float a0 = __expf(m0 - mn0);
        const float a1 = __expf(m1 - mn1);
        float rs0 = 0.f, rs1 = 0.f;
#pragma unroll
        for (int nt = 0; nt < 8; nt++) {
            s[nt][0] = __expf(s[nt][0] - mn0);
            s[nt][1] = __expf(s[nt][1] - mn0);
            s[nt][2] = __expf(s[nt][2] - mn1);
            s[nt][3] = __expf(s[nt][3] - mn1);
            rs0 += s[nt][0] + s[nt][1];
            rs1 += s[nt][2] + s[nt][3];
        }
        rs0 += __shfl_xor_sync(0xffffffffu, rs0, 1);
        rs0 += __shfl_xor_sync(0xffffffffu, rs0, 2);
        rs1 += __shfl_xor_sync(0xffffffffu, rs1, 1);
        rs1 += __shfl_xor_sync(0xffffffffu, rs1, 2);
        l0s = l0s * a0 + rs0;
        l1s = l1s * a1 + rs1;
        m0 = mn0;
        m1 = mn1;
#pragma unroll
        for (int nt = 0; nt < 8; nt++) {
            O[nt][0] *= a0; O[nt][1] *= a0;
            O[nt][2] *= a1; O[nt][3] *= a1;
        }

        uint32_t ph[4][4], pl[4][4];
#pragma unroll
        for (int j = 0; j < 4; j++) {
            h2split(s[2 * j][0], s[2 * j][1], ph[j][0], pl[j][0]);
            h2split(s[2 * j][2], s[2 * j][3], ph[j][1], pl[j][1]);
            h2split(s[2 * j + 1][0], s[2 * j + 1][1], ph[j][2], pl[j][2]);
            h2split(s[2 * j + 1][2], s[2 * j + 1][3], ph[j][3], pl[j][3]);
        }

        // ---- O += P @ V' (2-pass) ----
        float Oc[8][4];
#pragma unroll
        for (int nt = 0; nt < 8; nt++)
#pragma unroll
            for (int x = 0; x < 4; x++) Oc[nt][x] = 0.f;

#pragma unroll
        for (int j = 0; j < 4; j++) {
            const uint32_t krow = vhbase + j * 16 * VS_ + vrow_off;
#pragma unroll
            for (int np = 0; np < 4; np++) {
                uint32_t vh0, vh1, vh2, vh3;
                ldsm_x4_t(vh0, vh1, vh2, vh3, krow + np * 32);
                const int nt = np * 2;
                mma_f16(O[nt], ph[j][0], ph[j][1], ph[j][2], ph[j][3], vh0, vh1);
                mma_f16(Oc[nt], pl[j][0], pl[j][1], pl[j][2], pl[j][3], vh0, vh1);
                mma_f16(O[nt + 1], ph[j][0], ph[j][1], ph[j][2], ph[j][3], vh2, vh3);
                mma_f16(Oc[nt + 1], pl[j][0], pl[j][1], pl[j][2], pl[j][3], vh2, vh3);
            }
        }

#pragma unroll
        for (int nt = 0; nt < 8; nt++)
#pragma unroll
            for (int x = 0; x < 4; x++) O[nt][x] += Oc[nt][x] * inv2048;

        if (pf) {
            const int ns = stage ^ 1;
            char* kdst = smem + SM_K_ + ns * 20480;
            char* vdst = smem + SM_V_ + ns * VSTG_;
#pragma unroll
            for (int j = 0; j < 4; j++) {
                const int r = frow + 16 * j;
                *(uint4*)(kdst + r * QKS_ + f4 * 16) = pk[j];
                char* vh = vdst + r * VS_ + f4 * 8;
                *(uint2*)(vh) =
                    make_uint2(h2pack(pv[j].x, pv[j].y), h2pack(pv[j].z, pv[j].w));
            }
        }
        __syncthreads();
    }

    // ---- epilogue: V scale per column, normalize, write ctx IMAGE ----
    const int b = bh >> 5;
    const int h = bh & 31;
    const float i0 = 1.0f / l0s;
    const float i1 = 1.0f / l1s;
    char* row0p = ctxi + (size_t)(b * T_ + r0g) * 8192;
    char* row1p = ctxi + (size_t)(b * T_ + r1g) * 8192;
#pragma unroll
    for (int nt = 0; nt < 8; nt++) {
        const int d0 = nt * 8 + tg * 2;
        const float vs0 = VS[bh * 64 + d0];
        const float vs1 = VS[bh * 64 + d0 + 1];
        const int k = h * 64 + d0;
        const int chunk = k >> 5;
        const int p = (k & 31) >> 1;
        const int off = (p >> 3) * 64 + (p & 3) * 16 + ((p >> 2) & 1) * 4;
        uint32_t hh, ll;
        h2split(O[nt][0] * i0 * vs0, O[nt][1] * i0 * vs1, hh, ll);
        *(uint32_t*)(row0p + chunk * 128 + off) = hh;
        *(uint32_t*)(row0p + chunk * 128 + off + 8) = ll;
        h2split(O[nt][2] * i1 * vs0, O[nt][3] * i1 * vs1, hh, ll);
        *(uint32_t*)(row1p + chunk * 128 + off) = hh;
        *(uint32_t*)(row1p + chunk * 128 + off + 8) = ll;
    }
}

// ---------------------------------------------------------------------------
extern "C" void kernel_launch(void* const* d_in, const int* in_sizes, int n_in,
                              void* d_out, int out_size)
{
    (void)in_sizes; (void)n_in; (void)out_size;
    const float* hs = (const float*)d_in[0];
    const float* wq = (const float*)d_in[1];
    const float* bq = (const float*)d_in[2];
    const float* wk = (const float*)d_in[3];
    const float* bk = (const float*)d_in[4];
    const float* wv = (const float*)d_in[5];
    const float* bv = (const float*)d_in[6];
    const float* wo = (const float*)d_in[7];
    const float* bo = (const float*)d_in[8];
    float* out = (float*)d_out;

    float *q, *k, *v, *s, *vs;
    char *hsi, *wi, *ctxi, *qi, *ki;
    cudaGetSymbolAddress((void**)&q, g_q);
    cudaGetSymbolAddress((void**)&k, g_k);
    cudaGetSymbolAddress((void**)&v, g_v);
    cudaGetSymbolAddress((void**)&s, g_s);
    cudaGetSymbolAddress((void**)&vs, g_vs);
    cudaGetSymbolAddress((void**)&hsi, g_hsi);
    cudaGetSymbolAddress((void**)&wi, g_wi);
    cudaGetSymbolAddress((void**)&ctxi, g_ctxi);
    cudaGetSymbolAddress((void**)&qi, g_qi);
    cudaGetSymbolAddress((void**)&ki, g_ki);

    cudaFuncSetAttribute(qkv_gemm, cudaFuncAttributeMaxDynamicSharedMemorySize,
                         GEMM_SMEM_);
    cudaFuncSetAttribute(out_gemm, cudaFuncAttributeMaxDynamicSharedMemorySize,
                         GEMM_SMEM_);
    cudaFuncSetAttribute(attn_mma, cudaFuncAttributeMaxDynamicSharedMemorySize,
                         ATTN_SMEM_);

    // split hs + 4 weights into hi/lo fp16 fragment images
    split_all<<<(BT_ + 4 * E_) * 512 / 256, 256>>>(hs, wq, wk, wv, wo, hsi, wi);

    const size_t WPITCH = (size_t)E_ * E_ * 4 / 16;

    // merged QKV projections
    qkv_gemm<<<dim3(48, 32), 256, GEMM_SMEM_>>>(
        (const uint4*)hsi, (const uint4*)wi, bq, bk, bv, q, k, v);

    // SmoothK scale; quantize Q/K into images; V -> integer levels + scale
    smooth_absmax<<<BH_, 256>>>(k, s);
    row_quant_img<true><<<BH_ * T_ / 8, 256>>>(k, s, ki);
    row_quant_img<false><<<BH_ * T_ / 8, 256>>>(q, nullptr, qi);
    v_quant<<<BH_, 256>>>(v, vs);

    // fused tensor-core causal attention
    attn_mma<<<dim3(8, BH_), 256, ATTN_SMEM_>>>(
        (const uint4*)qi, (const uint4*)ki, v, vs, ctxi);

    // output projection
    out_gemm<<<dim3(16, 32), 256, GEMM_SMEM_>>>(
        (const uint4*)ctxi, (const uint4*)wi + 3 * WPITCH, bo, out);
}

// round 16
// speedup vs baseline: 1.0869x; 1.0869x over previous
#include <cuda_runtime.h>
#include <cuda_fp16.h>
#include <math.h>
#include <stdint.h>

// Problem constants
static const int B_ = 4;
static const int T_ = 1024;
static const int E_ = 2048;
static const int H_ = 32;
static const int D_ = 64;
static const int BT_ = B_ * T_;      // 4096
static const int BH_ = B_ * H_;      // 128

// Scratch (device globals; no allocation allowed)
__device__ float g_q[BH_ * T_ * D_];    // [B,H,T,D] fp32 projections
__device__ float g_k[BH_ * T_ * D_];
__device__ float g_v[BH_ * T_ * D_];    // after v_quant: integer (q-z) values
__device__ float g_s[BH_ * D_];         // SmoothK per-channel scale
__device__ float g_vs[BH_ * D_];        // V quant scale per (bh,d)
__device__ char g_hsi[BT_ * E_ * 4];    // hs image (hi/lo fp16 fragment layout)
__device__ char g_wi[4 * E_ * E_ * 4];  // wq,wk,wv,wo images
__device__ char g_ctxi[BT_ * E_ * 4];   // ctx image (written by attention)
__device__ char g_qi[BH_ * T_ * 256];   // quantized Q image (256B per row)
__device__ char g_ki[BH_ * T_ * 256];   // quantized K image

// ============================================================================
// common helpers
// ============================================================================
__device__ __forceinline__ void mma_f16(float* c, uint32_t a0, uint32_t a1,
                                        uint32_t a2, uint32_t a3,
                                        uint32_t b0, uint32_t b1) {
    asm volatile(
        "mma.sync.aligned.m16n8k16.row.col.f32.f16.f16.f32 "
        "{%0,%1,%2,%3}, {%4,%5,%6,%7}, {%8,%9}, {%0,%1,%2,%3};"
        : "+f"(c[0]), "+f"(c[1]), "+f"(c[2]), "+f"(c[3])
        : "r"(a0), "r"(a1), "r"(a2), "r"(a3), "r"(b0), "r"(b1));
}

// split two floats -> packed hi half2 and lo half2 (lo pre-scaled by 2048)
__device__ __forceinline__ void h2split(float x, float y, uint32_t& h,
                                        uint32_t& l) {
    __half2 hh = __floats2half2_rn(x, y);
    float2 hf = __half22float2(hh);
    __half2 ll = __floats2half2_rn((x - hf.x) * 2048.f, (y - hf.y) * 2048.f);
    h = *(uint32_t*)&hh;
    l = *(uint32_t*)&ll;
}

__device__ __forceinline__ uint32_t h2pack(float x, float y) {
    __half2 hh = __floats2half2_rn(x, y);
    return *(uint32_t*)&hh;
}

__device__ __forceinline__ void ldsm_x4_t(uint32_t& r0, uint32_t& r1,
                                          uint32_t& r2, uint32_t& r3,
                                          uint32_t addr) {
    asm volatile(
        "ldmatrix.sync.aligned.m8n8.x4.trans.shared.b16 {%0,%1,%2,%3}, [%4];"
        : "=r"(r0), "=r"(r1), "=r"(r2), "=r"(r3) : "r"(addr));
}

__device__ __forceinline__ uint32_t smem_u32(const void* p) {
    uint32_t a;
    asm("{ .reg .u64 t; cvta.to.shared.u64 t, %1; cvt.u32.u64 %0, t; }"
        : "=r"(a) : "l"(p));
    return a;
}

// ============================================================================
// split kernel: fp32 row-major -> hi/lo fp16 fragment-image layout.
// ============================================================================
__global__ __launch_bounds__(256) void split_all(
    const float* __restrict__ hs,
    const float* __restrict__ w0, const float* __restrict__ w1,
    const float* __restrict__ w2, const float* __restrict__ w3,
    char* __restrict__ hsi, char* __restrict__ wi)
{
    const int idx = blockIdx.x * 256 + threadIdx.x;
    const int row = idx >> 9;
    const int f = idx & 511;

    const float* src;
    char* dst;
    if (row < BT_) {
        src = hs + (size_t)row * E_;
        dst = hsi + (size_t)row * 8192;
    } else {
        const int r2 = row - BT_;
        const int w = r2 >> 11;
        const int wr = r2 & 2047;
        src = ((w == 0) ? w0 : (w == 1) ? w1 : (w == 2) ? w2 : w3) +
              (size_t)wr * E_;
        dst = wi + ((size_t)w * E_ + wr) * 8192;
    }

    float4 v = *(const float4*)(src + f * 4);
    const int chunk = f >> 3;
    const int k4 = f & 7;
    const int ks_f = k4 >> 2;
    const int p0 = (2 * k4) & 7;
    const int p1 = p0 + 1;
    const int off0 = ks_f * 64 + (p0 & 3) * 16 + ((p0 >> 2) & 1) * 4;
    const int off1 = ks_f * 64 + (p1 & 3) * 16 + ((p1 >> 2) & 1) * 4;

    uint32_t h0, l0, h1, l1;
    h2split(v.x, v.y, h0, l0);
    h2split(v.z, v.w, h1, l1);
    char* d = dst + chunk * 128;
    *(uint32_t*)(d + off0) = h0;
    *(uint32_t*)(d + off1) = h1;
    *(uint32_t*)(d + off0 + 8) = l0;
    *(uint32_t*)(d + off1 + 8) = l1;
}

// ============================================================================
// fp16 two-term-split GEMM via mma.sync.m16n8k16 from pre-split images.
// R14 structure exactly: 256 threads, 8 warps (2m x 4n), warp tile 64x32,
// 2-stage double buffer, pure-copy fill (LDG.128 -> STS.128).
// ============================================================================
static const int NCH_ = 64;
static const int RSB_ = 192;
static const int OPBYTES_ = 128 * RSB_;
static const int GEMM_SMEM_ = 4 * OPBYTES_;

template <int MODE>
__global__ __launch_bounds__(256, 1) void tc_gemm(
    const uint4* __restrict__ Aimg, const uint4* __restrict__ Wimg,
    const float* __restrict__ bias, float* __restrict__ C, float scale)
{
    extern __shared__ char smem[];

    const int tid = threadIdx.x;
    const int wid = tid >> 5;
    const int lane = tid & 31;
    const int bm = blockIdx.y * 128;
    const int bn = blockIdx.x * 128;

    const int wm = (wid & 1) * 64;
    const int wn = (wid >> 1) * 32;
    const int gq = lane >> 2;
    const int tg = lane & 3;

    const int row0 = tid >> 3;
    const int grp = tid & 7;
    size_t goffA[4], goffB[4];
    int stsOff[4];
#pragma unroll
    for (int j = 0; j < 4; j++) {
        const int r = row0 + 32 * j;
        stsOff[j] = r * RSB_ + grp * 16;
        goffA[j] = (size_t)(bm + r) * 512 + grp;
        goffB[j] = (size_t)(bn + r) * 512 + grp;
    }

    float accM[4][4][4], accC[4][4][4];
#pragma unroll
    for (int mt = 0; mt < 4; mt++)
#pragma unroll
        for (int nt = 0; nt < 4; nt++)
#pragma unroll
            for (int x = 0; x < 4; x++) {
                accM[mt][nt][x] = 0.f;
                accC[mt][nt][x] = 0.f;
            }

    {
        char* sA = smem;
        char* sB = smem + 2 * OPBYTES_;
#pragma unroll
        for (int j = 0; j < 4; j++) {
            *(uint4*)(sA + stsOff[j]) = Aimg[goffA[j]];
            *(uint4*)(sB + stsOff[j]) = Wimg[goffB[j]];
        }
    }
    __syncthreads();

    for (int c = 0; c < NCH_; c++) {
        uint4 pa[4], pb[4];
        const bool pf = (c + 1 < NCH_);
        if (pf) {
            const int co = (c + 1) * 8;
#pragma unroll
            for (int j = 0; j < 4; j++) {
                pa[j] = Aimg[goffA[j] + co];
                pb[j] = Wimg[goffB[j] + co];
            }
        }

        const char* sA = smem + (c & 1) * OPBYTES_;
        const char* sB = smem + 2 * OPBYTES_ + (c & 1) * OPBYTES_;
#pragma unroll
        for (int ks = 0; ks < 2; ks++) {
            uint4 bf[4];
#pragma unroll
            for (int nt = 0; nt < 4; nt++)
                bf[nt] = *(const uint4*)(sB + (wn + nt * 8 + gq) * RSB_ +
                                         ks * 64 + tg * 16);
#pragma unroll
            for (int mt = 0; mt < 4; mt++) {
                const char* ra =
                    sA + (wm + mt * 16 + gq) * RSB_ + ks * 64 + tg * 16;
                uint4 t = *(const uint4*)(ra);
                uint4 u = *(const uint4*)(ra + 8 * RSB_);
#pragma unroll
                for (int nt = 0; nt < 4; nt++) {
                    mma_f16(accM[mt][nt], t.x, u.x, t.y, u.y, bf[nt].x, bf[nt].y);
                    mma_f16(accC[mt][nt], t.z, u.z, t.w, u.w, bf[nt].x, bf[nt].y);
                    mma_f16(accC[mt][nt], t.x, u.x, t.y, u.y, bf[nt].z, bf[nt].w);
                }
            }
        }

        if (pf) {
            char* dA = smem + ((c + 1) & 1) * OPBYTES_;
            char* dB = smem + 2 * OPBYTES_ + ((c + 1) & 1) * OPBYTES_;
#pragma unroll
            for (int j = 0; j < 4; j++) {
                *(uint4*)(dA + stsOff[j]) = pa[j];
                *(uint4*)(dB + stsOff[j]) = pb[j];
            }
        }
        __syncthreads();
    }

    const float inv2048 = 1.0f / 2048.0f;
#pragma unroll
    for (int mt = 0; mt < 4; mt++) {
#pragma unroll
        for (int nt = 0; nt < 4; nt++) {
            const int n0 = bn + wn + nt * 8 + tg * 2;
            const float b0 = bias[n0], b1 = bias[n0 + 1];
#pragma unroll
            for (int half = 0; half < 2; half++) {
                const int m = bm + wm + mt * 16 + gq + half * 8;
                float2 v;
                v.x = (accM[mt][nt][half * 2 + 0] +
                       accC[mt][nt][half * 2 + 0] * inv2048 + b0) * scale;
                v.y = (accM[mt][nt][half * 2 + 1] +
                       accC[mt][nt][half * 2 + 1] * inv2048 + b1) * scale;
                if (MODE == 0) {
                    *(float2*)(C + (size_t)m * E_ + n0) = v;
                } else {
                    const int b = m >> 10, t = m & 1023;
                    const int h = n0 >> 6, d0 = n0 & 63;
                    *(float2*)(C + (((size_t)(b * H_ + h)) * T_ + t) * D_ + d0) = v;
                }
            }
        }
    }
}

// ---------------------------------------------------------------------------
// SmoothK per-channel abs-max over tokens
// ---------------------------------------------------------------------------
__global__ __launch_bounds__(256) void smooth_absmax(
    const float* __restrict__ Kin, float* __restrict__ S)
{
    const int bh = blockIdx.x;
    const int dt = threadIdx.x >> 6;
    const int d = threadIdx.x & 63;
    const float* p = Kin + (size_t)bh * T_ * D_ + d;
    float m = 0.f;
    for (int t = dt; t < T_; t += 4) m = fmaxf(m, fabsf(p[(size_t)t * D_]));
    __shared__ float sm[4][64];
    sm[dt][d] = m;
    __syncthreads();
    if (dt == 0) {
        float r = fmaxf(fmaxf(sm[0][d], sm[1][d]), fmaxf(sm[2][d], sm[3][d]));
        S[bh * 64 + d] = fmaxf(r, 1e-5f);
    }
}

// ---------------------------------------------------------------------------
// Per-row asymmetric fake quant; writes the hi/lo fp16 IMAGE (256B per row).
// Image pair p (elements 2p,2p+1): chunk=p>>4, pp=p&15,
// off = chunk*128 + (pp>>3)*64 + (pp&3)*16 + ((pp>>2)&1)*4; hi@off, lo@off+8.
// (Layout validated on-hardware in R15 — rel_err identical.)
// ---------------------------------------------------------------------------
template <bool SMOOTH>
__global__ __launch_bounds__(256) void row_quant_img(
    const float* __restrict__ X, const float* __restrict__ S,
    char* __restrict__ IMG)
{
    const int row = blockIdx.x * 8 + (threadIdx.x >> 5);
    const int lane = threadIdx.x & 31;
    const float* p = X + (size_t)row * 64;

    float s0 = 1.f, s1 = 1.f;
    if (SMOOTH) {
        const int bh = row >> 10;
        s0 = S[bh * 64 + lane];
        s1 = S[bh * 64 + lane + 32];
    }
    float x0 = p[lane] / s0;
    float x1 = p[lane + 32] / s1;

    float mx = fmaxf(fmaxf(x0, x1), 0.f);
    float mn = fminf(fminf(x0, x1), 0.f);
#pragma unroll
    for (int o = 16; o > 0; o >>= 1) {
        mx = fmaxf(mx, __shfl_xor_sync(0xffffffffu, mx, o));
        mn = fminf(mn, __shfl_xor_sync(0xffffffffu, mn, o));
    }
    float scale = (mx - mn) / 255.0f;
    if (scale <= 0.f) scale = 1.f;
    const float zero = rintf(-mn / scale);
    float q0 = fminf(fmaxf(rintf(x0 / scale) + zero, 0.f), 255.f);
    float q1 = fminf(fmaxf(rintf(x1 / scale) + zero, 0.f), 255.f);
    const float v0 = scale * (q0 - zero) * s0;
    const float v1 = scale * (q1 - zero) * s1;

    const float w0 = __shfl_xor_sync(0xffffffffu, v0, 1);
    const float w1 = __shfl_xor_sync(0xffffffffu, v1, 1);
    if ((lane & 1) == 0) {
        char* dst = IMG + (size_t)row * 256;
        const int ppA = lane >> 1;
        const int offA = (ppA >> 3) * 64 + (ppA & 3) * 16 + ((ppA >> 2) & 1) * 4;
        uint32_t h, l;
        h2split(v0, w0, h, l);
        *(uint32_t*)(dst + offA) = h;
        *(uint32_t*)(dst + offA + 8) = l;
        h2split(v1, w1, h, l);
        *(uint32_t*)(dst + 128 + offA) = h;
        *(uint32_t*)(dst + 128 + offA + 8) = l;
    }
}

// ---------------------------------------------------------------------------
// V fake quant along the token axis (integer levels + scale).
// ---------------------------------------------------------------------------
__global__ __launch_bounds__(256) void v_quant(float* __restrict__ V,
                                               float* __restrict__ VS)
{
    const int bh = blockIdx.x;
    const int dt = threadIdx.x >> 6;
    const int d = threadIdx.x & 63;
    float* p = V + (size_t)bh * T_ * D_ + d;

    float mx = 0.f, mn = 0.f;
    for (int t = dt; t < T_; t += 4) {
        float x = p[(size_t)t * D_];
        mx = fmaxf(mx, x);
        mn = fminf(mn, x);
    }
    __shared__ float smx[4][64], smn[4][64];
    smx[dt][d] = mx; smn[dt][d] = mn;
    __syncthreads();
    mx = fmaxf(fmaxf(smx[0][d], smx[1][d]), fmaxf(smx[2][d], smx[3][d]));
    mn = fminf(fminf(smn[0][d], smn[1][d]), fminf(smn[2][d], smn[3][d]));

    float scale = (mx - mn) / 255.0f;
    if (scale <= 0.f) scale = 1.f;
    const float zero = rintf(-mn / scale);
    if (dt == 0) VS[bh * 64 + d] = scale;
    for (int t = dt; t < T_; t += 4) {
        float x = p[(size_t)t * D_];
        float q = fminf(fmaxf(rintf(x / scale) + zero, 0.f), 255.f);
        p[(size_t)t * D_] = q - zero;
    }
}

// ============================================================================
// Tensor-core flash attention: Q/K from pre-quantized images (pure copies);
// V exact-integer fp16 (2-pass PV, scale at epilogue); writes ctx image.
// ============================================================================
static const int QKS_ = 320;
static const int VS_ = 144;
static const int SM_Q_ = 0;
static const int SM_K_ = 40960;
static const int SM_V_ = 81920;
static const int VSTG_ = 9216;
static const int ATTN_SMEM_ = SM_V_ + 2 * VSTG_;

__global__ __launch_bounds__(256, 1) void attn_mma(
    const uint4* __restrict__ Qi, const uint4* __restrict__ Ki,
    const float* __restrict__ Vb, const float* __restrict__ VS,
    char* __restrict__ ctxi)
{
    extern __shared__ char smem[];
    const uint32_t sb = smem_u32(smem);

    const int bh = blockIdx.y;
    const int qt = 7 - blockIdx.x;
    const int tid = threadIdx.x;
    const int wid = tid >> 5;
    const int lane = tid & 31;
    const int gq = lane >> 2;
    const int tg = lane & 3;
    const size_t base = (size_t)bh * T_;

    const int frow = tid >> 4;
    const int f4 = tid & 15;

    // ---- fill Q tile (pure copy) ----
#pragma unroll
    for (int j = 0; j < 8; j++) {
        const int r = frow + 16 * j;
        *(uint4*)(smem + SM_Q_ + r * QKS_ + f4 * 16) =
            Qi[(base + qt * 128 + r) * 16 + f4];
    }

    // ---- fill K/V ktile 0, stage 0 ----
#pragma unroll
    for (int j = 0; j < 4; j++) {
        const int r = frow + 16 * j;
        *(uint4*)(smem + SM_K_ + r * QKS_ + f4 * 16) = Ki[(base + r) * 16 + f4];
        float4 vv = *(const float4*)(Vb + (base + r) * D_ + f4 * 4);
        char* vh = smem + SM_V_ + r * VS_ + f4 * 8;
        *(uint2*)(vh) = make_uint2(h2pack(vv.x, vv.y), h2pack(vv.z, vv.w));
    }
    __syncthreads();

    float O[8][4];
#pragma unroll
    for (int nt = 0; nt < 8; nt++)
#pragma unroll
        for (int x = 0; x < 4; x++) O[nt][x] = 0.f;
    float m0 = -1e30f, m1 = -1e30f, l0s = 0.f, l1s = 0.f;

    const int r0g = qt * 128 + wid * 16 + gq;
    const int r1g = r0g + 8;
    const int nkt = 2 * (qt + 1);
    const float inv2048 = 1.0f / 2048.0f;
    const int vrow_off = (lane & 15) * VS_ + (lane >> 4) * 16;

    for (int kt = 0; kt < nkt; kt++) {
        const int stage = kt & 1;
        const uint32_t kbase = sb + SM_K_ + stage * 20480;
        const uint32_t vhbase = sb + SM_V_ + stage * VSTG_;

        uint4 pk[4];
        float4 pv[4];
        const bool pf = (kt + 1 < nkt);
        if (pf) {
            const size_t tok0 = (size_t)(kt + 1) * 64;
#pragma unroll
            for (int j = 0; j < 4; j++) {
                const size_t r = tok0 + frow + 16 * j;
                pk[j] = Ki[(base + r) * 16 + f4];
                pv[j] = *(const float4*)(Vb + (base + r) * D_ + f4 * 4);
            }
        }

        // ---- S = Q @ K^T (3-pass) ----
        float sm_[8][4], sc_[8][4];
#pragma unroll
        for (int nt = 0; nt < 8; nt++)
#pragma unroll
            for (int x = 0; x < 4; x++) { sm_[nt][x] = 0.f; sc_[nt][x] = 0.f; }

        const uint32_t qbase = sb + SM_Q_ + (wid * 16 + gq) * QKS_;
#pragma unroll
        for (int ks = 0; ks < 4; ks++) {
            uint4 tq, uq;
            asm volatile("ld.shared.v4.b32 {%0,%1,%2,%3}, [%4];"
                         : "=r"(tq.x), "=r"(tq.y), "=r"(tq.z), "=r"(tq.w)
                         : "r"(qbase + ks * 64 + tg * 16));
            asm volatile("ld.shared.v4.b32 {%0,%1,%2,%3}, [%4];"
                         : "=r"(uq.x), "=r"(uq.y), "=r"(uq.z), "=r"(uq.w)
                         : "r"(qbase + 8 * QKS_ + ks * 64 + tg * 16));
#pragma unroll
            for (int nt = 0; nt < 8; nt++) {
                uint4 bk;
                asm volatile("ld.shared.v4.b32 {%0,%1,%2,%3}, [%4];"
                             : "=r"(bk.x), "=r"(bk.y), "=r"(bk.z), "=r"(bk.w)
                             : "r"(kbase + (nt * 8 + gq) * QKS_ + ks * 64 + tg * 16));
                mma_f16(sm_[nt], tq.x, uq.x, tq.y, uq.y, bk.x, bk.y);
                mma_f16(sc_[nt], tq.z, uq.z, tq.w, uq.w, bk.x, bk.y);
                mma_f16(sc_[nt], tq.x, uq.x, tq.y, uq.y, bk.z, bk.w);
            }
        }

        float s[8][4];
        const bool maskit = (kt >= 2 * qt);
#pragma unroll
        for (int nt = 0; nt < 8; nt++)
#pragma unroll
            for (int x = 0; x < 4; x++) {
                float v = sm_[nt][x] + sc_[nt][x] * inv2048;
                if (maskit) {
                    const int col = kt * 64 + nt * 8 + tg * 2 + (x & 1);
                    const int row = (x < 2) ? r0g : r1g;
                    if (col > row) v = -INFINITY;
                }
                s[nt][x] = v;
            }

        // online softmax
        float rm0 = -1e30f, rm1 = -1e30f;
#pragma unroll
        for (int nt = 0; nt < 8; nt++) {
            rm0 = fmaxf(rm0, fmaxf(s[nt][0], s[nt][1]));
            rm1 = fmaxf(rm1, fmaxf(s[nt][2], s[nt][3]));
        }
        rm0 = fmaxf(rm0, __shfl_xor_sync(0xffffffffu, rm0, 1));
        rm0 = fmaxf(rm0, __shfl_xor_sync(0xffffffffu, rm0, 2));
        rm1 = fmaxf(rm1, __shfl_xor_sync(0xffffffffu, rm1, 1));
        rm1 = fmaxf(rm1, __shfl_xor_sync(0xffffffffu, rm1, 2));

        const float mn0 = fmaxf(m0, rm0);
        const float mn1 = fmaxf(m1, rm1);
        const float a0 = __expf(m0 - mn0);
        const float a1 = __expf(m1 - mn1);
        float rs0 = 0.f, rs1 = 0.f;
#pragma unroll
        for (int nt = 0; nt < 8; nt++) {
            s[nt][0] = __expf(s[nt][0] - mn0);
            s[nt][1] = __expf(s[nt][1] - mn0);
            s[nt][2] = __expf(s[nt][2] - mn1);
            s[nt][3] = __expf(s[nt][3] - mn1);
            rs0 += s[nt][0] + s[nt][1];
            rs1 += s[nt][2] + s[nt][3];
        }
        rs0 += __shfl_xor_sync(0xffffffffu, rs0, 1);
        rs0 += __shfl_xor_sync(0xffffffffu, rs0, 2);
        rs1 += __shfl_xor_sync(0xffffffffu, rs1, 1);
        rs1 += __shfl_xor_sync(0xffffffffu, rs1, 2);
        l0s = l0s * a0 + rs0;
        l1s = l1s * a1 + rs1;
        m0 = mn0;
        m1 = mn1;
#pragma unroll
        for (int nt = 0; nt < 8; nt++) {
            O[nt][0] *= a0; O[nt][1] *= a0;
            O[nt][2] *= a1; O[nt][3] *= a1;
        }

        uint32_t ph[4][4], pl[4][4];
#pragma unroll
        for (int j = 0; j < 4; j++) {
            h2split(s[2 * j][0], s[2 * j][1], ph[j][0], pl[j][0]);
            h2split(s[2 * j][2], s[2 * j][3], ph[j][1], pl[j][1]);
            h2split(s[2 * j + 1][0], s[2 * j + 1][1], ph[j][2], pl[j][2]);
            h2split(s[2 * j + 1][2], s[2 * j + 1][3], ph[j][3], pl[j][3]);
        }

        // ---- O += P @ V' (2-pass) ----
        float Oc[8][4];
#pragma unroll
        for (int nt = 0; nt < 8; nt++)
#pragma unroll
            for (int x = 0; x < 4; x++) Oc[nt][x] = 0.f;

#pragma unroll
        for (int j = 0; j < 4; j++) {
            const uint32_t krow = vhbase + j * 16 * VS_ + vrow_off;
#pragma unroll
            for (int np = 0; np < 4; np++) {
                uint32_t vh0, vh1, vh2, vh3;
                ldsm_x4_t(vh0, vh1, vh2, vh3, krow + np * 32);
                const int nt = np * 2;
                mma_f16(O[nt], ph[j][0], ph[j][1], ph[j][2], ph[j][3], vh0, vh1);
                mma_f16(Oc[nt], pl[j][0], pl[j][1], pl[j][2], pl[j][3], vh0, vh1);
                mma_f16(O[nt + 1], ph[j][0], ph[j][1], ph[j][2], ph[j][3], vh2, vh3);
                mma_f16(Oc[nt + 1], pl[j][0], pl[j][1], pl[j][2], pl[j][3], vh2, vh3);
            }
        }

#pragma unroll
        for (int nt = 0; nt < 8; nt++)
#pragma unroll
            for (int x = 0; x < 4; x++) O[nt][x] += Oc[nt][x] * inv2048;

        if (pf) {
            const int ns = stage ^ 1;
            char* kdst = smem + SM_K_ + ns * 20480;
            char* vdst = smem + SM_V_ + ns * VSTG_;
#pragma unroll
            for (int j = 0; j < 4; j++) {
                const int r = frow + 16 * j;
                *(uint4*)(kdst + r * QKS_ + f4 * 16) = pk[j];
                char* vh = vdst + r * VS_ + f4 * 8;
                *(uint2*)(vh) =
                    make_uint2(h2pack(pv[j].x, pv[j].y), h2pack(pv[j].z, pv[j].w));
            }
        }
        __syncthreads();
    }

    // ---- epilogue: V scale per column, normalize, write ctx IMAGE ----
    const int b = bh >> 5;
    const int h = bh & 31;
    const float i0 = 1.0f / l0s;
    const float i1 = 1.0f / l1s;
    char* row0p = ctxi + (size_t)(b * T_ + r0g) * 8192;
    char* row1p = ctxi + (size_t)(b * T_ + r1g) * 8192;
#pragma unroll
    for (int nt = 0; nt < 8; nt++) {
        const int d0 = nt * 8 + tg * 2;
        const float vs0 = VS[bh * 64 + d0];
        const float vs1 = VS[bh * 64 + d0 + 1];
        const int k = h * 64 + d0;
        const int chunk = k >> 5;
        const int p = (k & 31) >> 1;
        const int off = (p >> 3) * 64 + (p & 3) * 16 + ((p >> 2) & 1) * 4;
        uint32_t hh, ll;
        h2split(O[nt][0] * i0 * vs0, O[nt][1] * i0 * vs1, hh, ll);
        *(uint32_t*)(row0p + chunk * 128 + off) = hh;
        *(uint32_t*)(row0p + chunk * 128 + off + 8) = ll;
        h2split(O[nt][2] * i1 * vs0, O[nt][3] * i1 * vs1, hh, ll);
        *(uint32_t*)(row1p + chunk * 128 + off) = hh;
        *(uint32_t*)(row1p + chunk * 128 + off + 8) = ll;
    }
}

// ---------------------------------------------------------------------------
extern "C" void kernel_launch(void* const* d_in, const int* in_sizes, int n_in,
                              void* d_out, int out_size)
{
    (void)in_sizes; (void)n_in; (void)out_size;
    const float* hs = (const float*)d_in[0];
    const float* wq = (const float*)d_in[1];
    const float* bq = (const float*)d_in[2];
    const float* wk = (const float*)d_in[3];
    const float* bk = (const float*)d_in[4];
    const float* wv = (const float*)d_in[5];
    const float* bv = (const float*)d_in[6];
    const float* wo = (const float*)d_in[7];
    const float* bo = (const float*)d_in[8];
    float* out = (float*)d_out;

    float *q, *k, *v, *s, *vs;
    char *hsi, *wi, *ctxi, *qi, *ki;
    cudaGetSymbolAddress((void**)&q, g_q);
    cudaGetSymbolAddress((void**)&k, g_k);
    cudaGetSymbolAddress((void**)&v, g_v);
    cudaGetSymbolAddress((void**)&s, g_s);
    cudaGetSymbolAddress((void**)&vs, g_vs);
    cudaGetSymbolAddress((void**)&hsi, g_hsi);
    cudaGetSymbolAddress((void**)&wi, g_wi);
    cudaGetSymbolAddress((void**)&ctxi, g_ctxi);
    cudaGetSymbolAddress((void**)&qi, g_qi);
    cudaGetSymbolAddress((void**)&ki, g_ki);

    cudaFuncSetAttribute(tc_gemm<0>, cudaFuncAttributeMaxDynamicSharedMemorySize,
                         GEMM_SMEM_);
    cudaFuncSetAttribute(tc_gemm<1>, cudaFuncAttributeMaxDynamicSharedMemorySize,
                         GEMM_SMEM_);
    cudaFuncSetAttribute(attn_mma, cudaFuncAttributeMaxDynamicSharedMemorySize,
                         ATTN_SMEM_);

    // split hs + 4 weights into hi/lo fp16 fragment images
    split_all<<<(BT_ + 4 * E_) * 512 / 256, 256>>>(hs, wq, wk, wv, wo, hsi, wi);

    dim3 gemmGrid(E_ / 128, BT_ / 128);  // (16, 32)
    const size_t WPITCH = (size_t)E_ * E_ * 4 / 16;

    // QKV projections — separate launches (R14 arrangement, measured best)
    tc_gemm<1><<<gemmGrid, 256, GEMM_SMEM_>>>(
        (const uint4*)hsi, (const uint4*)wi, bq, q, 0.125f);
    tc_gemm<1><<<gemmGrid, 256, GEMM_SMEM_>>>(
        (const uint4*)hsi, (const uint4*)wi + WPITCH, bk, k, 1.0f);
    tc_gemm<1><<<gemmGrid, 256, GEMM_SMEM_>>>(
        (const uint4*)hsi, (const uint4*)wi + 2 * WPITCH, bv, v, 1.0f);

    // SmoothK scale; quantize Q/K into images; V -> integer levels + scale
    smooth_absmax<<<BH_, 256>>>(k, s);
    row_quant_img<true><<<BH_ * T_ / 8, 256>>>(k, s, ki);
    row_quant_img<false><<<BH_ * T_ / 8, 256>>>(q, nullptr, qi);
    v_quant<<<BH_, 256>>>(v, vs);

    // fused tensor-core causal attention (reads Q/K images, writes ctx image)
    attn_mma<<<dim3(8, BH_), 256, ATTN_SMEM_>>>(
        (const uint4*)qi, (const uint4*)ki, v, vs, ctxi);

    // output projection (consumes ctx image + wo image)
    tc_gemm<0><<<gemmGrid, 256, GEMM_SMEM_>>>(
        (const uint4*)ctxi, (const uint4*)wi + 3 * WPITCH, bo, out, 1.0f);
}

// round 17
// speedup vs baseline: 1.0883x; 1.0013x over previous
#include <cuda_runtime.h>
#include <cuda_fp16.h>
#include <math.h>
#include <stdint.h>

// Problem constants
static const int B_ = 4;
static const int T_ = 1024;
static const int E_ = 2048;
static const int H_ = 32;
static const int D_ = 64;
static const int BT_ = B_ * T_;      // 4096
static const int BH_ = B_ * H_;      // 128

// Scratch (device globals; no allocation allowed)
__device__ float g_q[BH_ * T_ * D_];    // [B,H,T,D] fp32 projections
__device__ float g_k[BH_ * T_ * D_];
__device__ float g_v[BH_ * T_ * D_];    // after stats: integer (q-z) values
__device__ float g_s[BH_ * D_];         // SmoothK per-channel scale
__device__ float g_vs[BH_ * D_];        // V quant scale per (bh,d)
__device__ char g_hsi[BT_ * E_ * 4];    // hs image (hi/lo fp16 fragment layout)
__device__ char g_wi[4 * E_ * E_ * 4];  // wq,wk,wv,wo images
__device__ char g_ctxi[BT_ * E_ * 4];   // ctx image (written by attention)
__device__ char g_qi[BH_ * T_ * 256];   // quantized Q image (256B per row)
__device__ char g_ki[BH_ * T_ * 256];   // quantized K image

// ============================================================================
// common helpers
// ============================================================================
__device__ __forceinline__ void mma_f16(float* c, uint32_t a0, uint32_t a1,
                                        uint32_t a2, uint32_t a3,
                                        uint32_t b0, uint32_t b1) {
    asm volatile(
        "mma.sync.aligned.m16n8k16.row.col.f32.f16.f16.f32 "
        "{%0,%1,%2,%3}, {%4,%5,%6,%7}, {%8,%9}, {%0,%1,%2,%3};"
        : "+f"(c[0]), "+f"(c[1]), "+f"(c[2]), "+f"(c[3])
        : "r"(a0), "r"(a1), "r"(a2), "r"(a3), "r"(b0), "r"(b1));
}

// split two floats -> packed hi half2 and lo half2 (lo pre-scaled by 2048)
__device__ __forceinline__ void h2split(float x, float y, uint32_t& h,
                                        uint32_t& l) {
    __half2 hh = __floats2half2_rn(x, y);
    float2 hf = __half22float2(hh);
    __half2 ll = __floats2half2_rn((x - hf.x) * 2048.f, (y - hf.y) * 2048.f);
    h = *(uint32_t*)&hh;
    l = *(uint32_t*)&ll;
}

__device__ __forceinline__ uint32_t h2pack(float x, float y) {
    __half2 hh = __floats2half2_rn(x, y);
    return *(uint32_t*)&hh;
}

__device__ __forceinline__ void ldsm_x4_t(uint32_t& r0, uint32_t& r1,
                                          uint32_t& r2, uint32_t& r3,
                                          uint32_t addr) {
    asm volatile(
        "ldmatrix.sync.aligned.m8n8.x4.trans.shared.b16 {%0,%1,%2,%3}, [%4];"
        : "=r"(r0), "=r"(r1), "=r"(r2), "=r"(r3) : "r"(addr));
}

__device__ __forceinline__ uint32_t smem_u32(const void* p) {
    uint32_t a;
    asm("{ .reg .u64 t; cvta.to.shared.u64 t, %1; cvt.u32.u64 %0, t; }"
        : "=r"(a) : "l"(p));
    return a;
}

// ============================================================================
// split kernel: fp32 row-major -> hi/lo fp16 fragment-image layout.
// ============================================================================
__global__ __launch_bounds__(256) void split_all(
    const float* __restrict__ hs,
    const float* __restrict__ w0, const float* __restrict__ w1,
    const float* __restrict__ w2, const float* __restrict__ w3,
    char* __restrict__ hsi, char* __restrict__ wi)
{
    const int idx = blockIdx.x * 256 + threadIdx.x;
    const int row = idx >> 9;
    const int f = idx & 511;

    const float* src;
    char* dst;
    if (row < BT_) {
        src = hs + (size_t)row * E_;
        dst = hsi + (size_t)row * 8192;
    } else {
        const int r2 = row - BT_;
        const int w = r2 >> 11;
        const int wr = r2 & 2047;
        src = ((w == 0) ? w0 : (w == 1) ? w1 : (w == 2) ? w2 : w3) +
              (size_t)wr * E_;
        dst = wi + ((size_t)w * E_ + wr) * 8192;
    }

    float4 v = *(const float4*)(src + f * 4);
    const int chunk = f >> 3;
    const int k4 = f & 7;
    const int ks_f = k4 >> 2;
    const int p0 = (2 * k4) & 7;
    const int p1 = p0 + 1;
    const int off0 = ks_f * 64 + (p0 & 3) * 16 + ((p0 >> 2) & 1) * 4;
    const int off1 = ks_f * 64 + (p1 & 3) * 16 + ((p1 >> 2) & 1) * 4;

    uint32_t h0, l0, h1, l1;
    h2split(v.x, v.y, h0, l0);
    h2split(v.z, v.w, h1, l1);
    char* d = dst + chunk * 128;
    *(uint32_t*)(d + off0) = h0;
    *(uint32_t*)(d + off1) = h1;
    *(uint32_t*)(d + off0 + 8) = l0;
    *(uint32_t*)(d + off1 + 8) = l1;
}

// ============================================================================
// fp16 two-term-split GEMM via mma.sync.m16n8k16 from pre-split images.
// R14 structure exactly (measured best): 256 threads, 8 warps (2m x 4n),
// warp tile 64x32, 2-stage double buffer, pure-copy fill.
// ============================================================================
static const int NCH_ = 64;
static const int RSB_ = 192;
static const int OPBYTES_ = 128 * RSB_;
static const int GEMM_SMEM_ = 4 * OPBYTES_;

template <int MODE>
__global__ __launch_bounds__(256, 1) void tc_gemm(
    const uint4* __restrict__ Aimg, const uint4* __restrict__ Wimg,
    const float* __restrict__ bias, float* __restrict__ C, float scale)
{
    extern __shared__ char smem[];

    const int tid = threadIdx.x;
    const int wid = tid >> 5;
    const int lane = tid & 31;
    const int bm = blockIdx.y * 128;
    const int bn = blockIdx.x * 128;

    const int wm = (wid & 1) * 64;
    const int wn = (wid >> 1) * 32;
    const int gq = lane >> 2;
    const int tg = lane & 3;

    const int row0 = tid >> 3;
    const int grp = tid & 7;
    size_t goffA[4], goffB[4];
    int stsOff[4];
#pragma unroll
    for (int j = 0; j < 4; j++) {
        const int r = row0 + 32 * j;
        stsOff[j] = r * RSB_ + grp * 16;
        goffA[j] = (size_t)(bm + r) * 512 + grp;
        goffB[j] = (size_t)(bn + r) * 512 + grp;
    }

    float accM[4][4][4], accC[4][4][4];
#pragma unroll
    for (int mt = 0; mt < 4; mt++)
#pragma unroll
        for (int nt = 0; nt < 4; nt++)
#pragma unroll
            for (int x = 0; x < 4; x++) {
                accM[mt][nt][x] = 0.f;
                accC[mt][nt][x] = 0.f;
            }

    {
        char* sA = smem;
        char* sB = smem + 2 * OPBYTES_;
#pragma unroll
        for (int j = 0; j < 4; j++) {
            *(uint4*)(sA + stsOff[j]) = Aimg[goffA[j]];
            *(uint4*)(sB + stsOff[j]) = Wimg[goffB[j]];
        }
    }
    __syncthreads();

    for (int c = 0; c < NCH_; c++) {
        uint4 pa[4], pb[4];
        const bool pf = (c + 1 < NCH_);
        if (pf) {
            const int co = (c + 1) * 8;
#pragma unroll
            for (int j = 0; j < 4; j++) {
                pa[j] = Aimg[goffA[j] + co];
                pb[j] = Wimg[goffB[j] + co];
            }
        }

        const char* sA = smem + (c & 1) * OPBYTES_;
        const char* sB = smem + 2 * OPBYTES_ + (c & 1) * OPBYTES_;
#pragma unroll
        for (int ks = 0; ks < 2; ks++) {
            uint4 bf[4];
#pragma unroll
            for (int nt = 0; nt < 4; nt++)
                bf[nt] = *(const uint4*)(sB + (wn + nt * 8 + gq) * RSB_ +
                                         ks * 64 + tg * 16);
#pragma unroll
            for (int mt = 0; mt < 4; mt++) {
                const char* ra =
                    sA + (wm + mt * 16 + gq) * RSB_ + ks * 64 + tg * 16;
                uint4 t = *(const uint4*)(ra);
                uint4 u = *(const uint4*)(ra + 8 * RSB_);
#pragma unroll
                for (int nt = 0; nt < 4; nt++) {
                    mma_f16(accM[mt][nt], t.x, u.x, t.y, u.y, bf[nt].x, bf[nt].y);
                    mma_f16(accC[mt][nt], t.z, u.z, t.w, u.w, bf[nt].x, bf[nt].y);
                    mma_f16(accC[mt][nt], t.x, u.x, t.y, u.y, bf[nt].z, bf[nt].w);
                }
            }
        }

        if (pf) {
            char* dA = smem + ((c + 1) & 1) * OPBYTES_;
            char* dB = smem + 2 * OPBYTES_ + ((c + 1) & 1) * OPBYTES_;
#pragma unroll
            for (int j = 0; j < 4; j++) {
                *(uint4*)(dA + stsOff[j]) = pa[j];
                *(uint4*)(dB + stsOff[j]) = pb[j];
            }
        }
        __syncthreads();
    }

    const float inv2048 = 1.0f / 2048.0f;
#pragma unroll
    for (int mt = 0; mt < 4; mt++) {
#pragma unroll
        for (int nt = 0; nt < 4; nt++) {
            const int n0 = bn + wn + nt * 8 + tg * 2;
            const float b0 = bias[n0], b1 = bias[n0 + 1];
#pragma unroll
            for (int half = 0; half < 2; half++) {
                const int m = bm + wm + mt * 16 + gq + half * 8;
                float2 v;
                v.x = (accM[mt][nt][half * 2 + 0] +
                       accC[mt][nt][half * 2 + 0] * inv2048 + b0) * scale;
                v.y = (accM[mt][nt][half * 2 + 1] +
                       accC[mt][nt][half * 2 + 1] * inv2048 + b1) * scale;
                if (MODE == 0) {
                    *(float2*)(C + (size_t)m * E_ + n0) = v;
                } else {
                    const int b = m >> 10, t = m & 1023;
                    const int h = n0 >> 6, d0 = n0 & 63;
                    *(float2*)(C + (((size_t)(b * H_ + h)) * T_ + t) * D_ + d0) = v;
                }
            }
        }
    }
}

// ---------------------------------------------------------------------------
// Merged stats: bx<128 -> SmoothK abs-max over tokens (K); bx>=128 -> V quant
// (min/max over tokens, write integer levels in place + scale). Independent
// tensors, one launch (pattern validated in R8).
// ---------------------------------------------------------------------------
__global__ __launch_bounds__(256) void stats_kernel(
    const float* __restrict__ Kin, float* __restrict__ V,
    float* __restrict__ S, float* __restrict__ VS)
{
    const int isv = blockIdx.x >> 7;
    const int bh = blockIdx.x & 127;
    const int dt = threadIdx.x >> 6;
    const int d = threadIdx.x & 63;
    __shared__ float smx[4][64], smn[4][64];

    if (!isv) {
        const float* p = Kin + (size_t)bh * T_ * D_ + d;
        float m = 0.f;
        for (int t = dt; t < T_; t += 4) m = fmaxf(m, fabsf(p[(size_t)t * D_]));
        smx[dt][d] = m;
        __syncthreads();
        if (dt == 0) {
            float r = fmaxf(fmaxf(smx[0][d], smx[1][d]),
                            fmaxf(smx[2][d], smx[3][d]));
            S[bh * 64 + d] = fmaxf(r, 1e-5f);
        }
    } else {
        float* p = V + (size_t)bh * T_ * D_ + d;
        float mx = 0.f, mn = 0.f;
        for (int t = dt; t < T_; t += 4) {
            float x = p[(size_t)t * D_];
            mx = fmaxf(mx, x);
            mn = fminf(mn, x);
        }
        smx[dt][d] = mx;
        smn[dt][d] = mn;
        __syncthreads();
        mx = fmaxf(fmaxf(smx[0][d], smx[1][d]), fmaxf(smx[2][d], smx[3][d]));
        mn = fminf(fminf(smn[0][d], smn[1][d]), fminf(smn[2][d], smn[3][d]));

        float scale = (mx - mn) / 255.0f;
        if (scale <= 0.f) scale = 1.f;
        const float zero = rintf(-mn / scale);
        if (dt == 0) VS[bh * 64 + d] = scale;
        for (int t = dt; t < T_; t += 4) {
            float x = p[(size_t)t * D_];
            float q = fminf(fmaxf(rintf(x / scale) + zero, 0.f), 255.f);
            p[(size_t)t * D_] = q - zero;   // integer in [-255, 255]
        }
    }
}

// ---------------------------------------------------------------------------
// Merged Q+K per-row fake quant -> hi/lo fp16 images (256B per row).
// First half of grid handles Q (no smoothing), second half K (SmoothK).
// Image pair p: chunk=p>>4, pp=p&15,
// off = chunk*128 + (pp>>3)*64 + (pp&3)*16 + ((pp>>2)&1)*4; hi@off, lo@off+8.
// (Layout validated on-hardware in R15/R16.)
// ---------------------------------------------------------------------------
__global__ __launch_bounds__(256) void row_quant_img_qk(
    const float* __restrict__ Q, const float* __restrict__ K,
    const float* __restrict__ S,
    char* __restrict__ QI, char* __restrict__ KI)
{
    const int half_grid = BH_ * T_ / 8;   // 16384 blocks per tensor
    const bool isK = blockIdx.x >= half_grid;
    const int bx = isK ? (blockIdx.x - half_grid) : blockIdx.x;
    const int row = bx * 8 + (threadIdx.x >> 5);
    const int lane = threadIdx.x & 31;
    const float* p = (isK ? K : Q) + (size_t)row * 64;
    char* IMG = isK ? KI : QI;

    float s0 = 1.f, s1 = 1.f;
    if (isK) {
        const int bh = row >> 10;
        s0 = S[bh * 64 + lane];
        s1 = S[bh * 64 + lane + 32];
    }
    float x0 = p[lane] / s0;
    float x1 = p[lane + 32] / s1;

    float mx = fmaxf(fmaxf(x0, x1), 0.f);
    float mn = fminf(fminf(x0, x1), 0.f);
#pragma unroll
    for (int o = 16; o > 0; o >>= 1) {
        mx = fmaxf(mx, __shfl_xor_sync(0xffffffffu, mx, o));
        mn = fminf(mn, __shfl_xor_sync(0xffffffffu, mn, o));
    }
    float scale = (mx - mn) / 255.0f;
    if (scale <= 0.f) scale = 1.f;
    const float zero = rintf(-mn / scale);
    float q0 = fminf(fmaxf(rintf(x0 / scale) + zero, 0.f), 255.f);
    float q1 = fminf(fmaxf(rintf(x1 / scale) + zero, 0.f), 255.f);
    const float v0 = scale * (q0 - zero) * s0;
    const float v1 = scale * (q1 - zero) * s1;

    const float w0 = __shfl_xor_sync(0xffffffffu, v0, 1);
    const float w1 = __shfl_xor_sync(0xffffffffu, v1, 1);
    if ((lane & 1) == 0) {
        char* dst = IMG + (size_t)row * 256;
        const int ppA = lane >> 1;
        const int offA = (ppA >> 3) * 64 + (ppA & 3) * 16 + ((ppA >> 2) & 1) * 4;
        uint32_t h, l;
        h2split(v0, w0, h, l);
        *(uint32_t*)(dst + offA) = h;
        *(uint32_t*)(dst + offA + 8) = l;
        h2split(v1, w1, h, l);
        *(uint32_t*)(dst + 128 + offA) = h;
        *(uint32_t*)(dst + 128 + offA + 8) = l;
    }
}

// ============================================================================
// Tensor-core flash attention: Q/K from pre-quantized images (pure copies);
// V exact-integer fp16 (2-pass PV, scale at epilogue); writes ctx image.
// (R16 version, measured best.)
// ============================================================================
static const int QKS_ = 320;
static const int VS_ = 144;
static const int SM_Q_ = 0;
static const int SM_K_ = 40960;
static const int SM_V_ = 81920;
static const int VSTG_ = 9216;
static const int ATTN_SMEM_ = SM_V_ + 2 * VSTG_;

__global__ __launch_bounds__(256, 1) void attn_mma(
    const uint4* __restrict__ Qi, const uint4* __restrict__ Ki,
    const float* __restrict__ Vb, const float* __restrict__ VS,
    char* __restrict__ ctxi)
{
    extern __shared__ char smem[];
    const uint32_t sb = smem_u32(smem);

    const int bh = blockIdx.y;
    const int qt = 7 - blockIdx.x;
    const int tid = threadIdx.x;
    const int wid = tid >> 5;
    const int lane = tid & 31;
    const int gq = lane >> 2;
    const int tg = lane & 3;
    const size_t base = (size_t)bh * T_;

    const int frow = tid >> 4;
    const int f4 = tid & 15;

    // ---- fill Q tile (pure copy) ----
#pragma unroll
    for (int j = 0; j < 8; j++) {
        const int r = frow + 16 * j;
        *(uint4*)(smem + SM_Q_ + r * QKS_ + f4 * 16) =
            Qi[(base + qt * 128 + r) * 16 + f4];
    }

    // ---- fill K/V ktile 0, stage 0 ----
#pragma unroll
    for (int j = 0; j < 4; j++) {
        const int r = frow + 16 * j;
        *(uint4*)(smem + SM_K_ + r * QKS_ + f4 * 16) = Ki[(base + r) * 16 + f4];
        float4 vv = *(const float4*)(Vb + (base + r) * D_ + f4 * 4);
        char* vh = smem + SM_V_ + r * VS_ + f4 * 8;
        *(uint2*)(vh) = make_uint2(h2pack(vv.x, vv.y), h2pack(vv.z, vv.w));
    }
    __syncthreads();

    float O[8][4];
#pragma unroll
    for (int nt = 0; nt < 8; nt++)
#pragma unroll
        for (int x = 0; x < 4; x++) O[nt][x] = 0.f;
    float m0 = -1e30f, m1 = -1e30f, l0s = 0.f, l1s = 0.f;

    const int r0g = qt * 128 + wid * 16 + gq;
    const int r1g = r0g + 8;
    const int nkt = 2 * (qt + 1);
    const float inv2048 = 1.0f / 2048.0f;
    const int vrow_off = (lane & 15) * VS_ + (lane >> 4) * 16;

    for (int kt = 0; kt < nkt; kt++) {
        const int stage = kt & 1;
        const uint32_t kbase = sb + SM_K_ + stage * 20480;
        const uint32_t vhbase = sb + SM_V_ + stage * VSTG_;

        uint4 pk[4];
        float4 pv[4];
        const bool pf = (kt + 1 < nkt);
        if (pf) {
            const size_t tok0 = (size_t)(kt + 1) * 64;
#pragma unroll
            for (int j = 0; j < 4; j++) {
                const size_t r = tok0 + frow + 16 * j;
                pk[j] = Ki[(base + r) * 16 + f4];
                pv[j] = *(const float4*)(Vb + (base + r) * D_ + f4 * 4);
            }
        }

        // ---- S = Q @ K^T (3-pass) ----
        float sm_[8][4], sc_[8][4];
#pragma unroll
        for (int nt = 0; nt < 8; nt++)
#pragma unroll
            for (int x = 0; x < 4; x++) { sm_[nt][x] = 0.f; sc_[nt][x] = 0.f; }

        const uint32_t qbase = sb + SM_Q_ + (wid * 16 + gq) * QKS_;
#pragma unroll
        for (int ks = 0; ks < 4; ks++) {
            uint4 tq, uq;
            asm volatile("ld.shared.v4.b32 {%0,%1,%2,%3}, [%4];"
                         : "=r"(tq.x), "=r"(tq.y), "=r"(tq.z), "=r"(tq.w)
                         : "r"(qbase + ks * 64 + tg * 16));
            asm volatile("ld.shared.v4.b32 {%0,%1,%2,%3}, [%4];"
                         : "=r"(uq.x), "=r"(uq.y), "=r"(uq.z), "=r"(uq.w)
                         : "r"(qbase + 8 * QKS_ + ks * 64 + tg * 16));
#pragma unroll
            for (int nt = 0; nt < 8; nt++) {
                uint4 bk;
                asm volatile("ld.shared.v4.b32 {%0,%1,%2,%3}, [%4];"
                             : "=r"(bk.x), "=r"(bk.y), "=r"(bk.z), "=r"(bk.w)
                             : "r"(kbase + (nt * 8 + gq) * QKS_ + ks * 64 + tg * 16));
                mma_f16(sm_[nt], tq.x, uq.x, tq.y, uq.y, bk.x, bk.y);
                mma_f16(sc_[nt], tq.z, uq.z, tq.w, uq.w, bk.x, bk.y);
                mma_f16(sc_[nt], tq.x, uq.x, tq.y, uq.y, bk.z, bk.w);
            }
        }

        float s[8][4];
        const bool maskit = (kt >= 2 * qt);
#pragma unroll
        for (int nt = 0; nt < 8; nt++)
#pragma unroll
            for (int x = 0; x < 4; x++) {
                float v = sm_[nt][x] + sc_[nt][x] * inv2048;
                if (maskit) {
                    const int col = kt * 64 + nt * 8 + tg * 2 + (x & 1);
                    const int row = (x < 2) ? r0g : r1g;
                    if (col > row) v = -INFINITY;
                }
                s[nt][x] = v;
            }

        // online softmax
        float rm0 = -1e30f, rm1 = -1e30f;
#pragma unroll
        for (int nt = 0; nt < 8; nt++) {
            rm0 = fmaxf(rm0, fmaxf(s[nt][0], s[nt][1]));
            rm1 = fmaxf(rm1, fmaxf(s[nt][2], s[nt][3]));
        }
        rm0 = fmaxf(rm0, __shfl_xor_sync(0xffffffffu, rm0, 1));
        rm0 = fmaxf(rm0, __shfl_xor_sync(0xffffffffu, rm0, 2));
        rm1 = fmaxf(rm1, __shfl_xor_sync(0xffffffffu, rm1, 1));
        rm1 = fmaxf(rm1, __shfl_xor_sync(0xffffffffu, rm1, 2));

        const float mn0 = fmaxf(m0, rm0);
        const float mn1 = fmaxf(m1, rm1);
        const float a0 = __expf(m0 - mn0);
        const float a1 = __expf(m1 - mn1);
        float rs0 = 0.f, rs1 = 0.f;
#pragma unroll
        for (int nt = 0; nt < 8; nt++) {
            s[nt][0] = __expf(s[nt][0] - mn0);
            s[nt][1] = __expf(s[nt][1] - mn0);
            s[nt][2] = __expf(s[nt][2] - mn1);
            s[nt][3] = __expf(s[nt][3] - mn1);
            rs0 += s[nt][0] + s[nt][1];
            rs1 += s[nt][2] + s[nt][3];
        }
        rs0 += __shfl_xor_sync(0xffffffffu, rs0, 1);
        rs0 += __shfl_xor_sync(0xffffffffu, rs0, 2);
        rs1 += __shfl_xor_sync(0xffffffffu, rs1, 1);
        rs1 += __shfl_xor_sync(0xffffffffu, rs1, 2);
        l0s = l0s * a0 + rs0;
        l1s = l1s * a1 + rs1;
        m0 = mn0;
        m1 = mn1;
#pragma unroll
        for (int nt = 0; nt < 8; nt++) {
            O[nt][0] *= a0; O[nt][1] *= a0;
            O[nt][2] *= a1; O[nt][3] *= a1;
        }

        uint32_t ph[4][4], pl[4][4];
#pragma unroll
        for (int j = 0; j < 4; j++) {
            h2split(s[2 * j][0], s[2 * j][1], ph[j][0], pl[j][0]);
            h2split(s[2 * j][2], s[2 * j][3], ph[j][1], pl[j][1]);
            h2split(s[2 * j + 1][0], s[2 * j + 1][1], ph[j][2], pl[j][2]);
            h2split(s[2 * j + 1][2], s[2 * j + 1][3], ph[j][3], pl[j][3]);
        }

        // ---- O += P @ V' (2-pass) ----
        float Oc[8][4];
#pragma unroll
        for (int nt = 0; nt < 8; nt++)
#pragma unroll
            for (int x = 0; x < 4; x++) Oc[nt][x] = 0.f;

#pragma unroll
        for (int j = 0; j < 4; j++) {
            const uint32_t krow = vhbase + j * 16 * VS_ + vrow_off;
#pragma unroll
            for (int np = 0; np < 4; np++) {
                uint32_t vh0, vh1, vh2, vh3;
                ldsm_x4_t(vh0, vh1, vh2, vh3, krow + np * 32);
                const int nt = np * 2;
                mma_f16(O[nt], ph[j][0], ph[j][1], ph[j][2], ph[j][3], vh0, vh1);
                mma_f16(Oc[nt], pl[j][0], pl[j][1], pl[j][2], pl[j][3], vh0, vh1);
                mma_f16(O[nt + 1], ph[j][0], ph[j][1], ph[j][2], ph[j][3], vh2, vh3);
                mma_f16(Oc[nt + 1], pl[j][0], pl[j][1], pl[j][2], pl[j][3], vh2, vh3);
            }
        }

#pragma unroll
        for (int nt = 0; nt < 8; nt++)
#pragma unroll
            for (int x = 0; x < 4; x++) O[nt][x] += Oc[nt][x] * inv2048;

        if (pf) {
            const int ns = stage ^ 1;
            char* kdst = smem + SM_K_ + ns * 20480;
            char* vdst = smem + SM_V_ + ns * VSTG_;
#pragma unroll
            for (int j = 0; j < 4; j++) {
                const int r = frow + 16 * j;
                *(uint4*)(kdst + r * QKS_ + f4 * 16) = pk[j];
                char* vh = vdst + r * VS_ + f4 * 8;
                *(uint2*)(vh) =
                    make_uint2(h2pack(pv[j].x, pv[j].y), h2pack(pv[j].z, pv[j].w));
            }
        }
        __syncthreads();
    }

    // ---- epilogue: V scale per column, normalize, write ctx IMAGE ----
    const int b = bh >> 5;
    const int h = bh & 31;
    const float i0 = 1.0f / l0s;
    const float i1 = 1.0f / l1s;
    char* row0p = ctxi + (size_t)(b * T_ + r0g) * 8192;
    char* row1p = ctxi + (size_t)(b * T_ + r1g) * 8192;
#pragma unroll
    for (int nt = 0; nt < 8; nt++) {
        const int d0 = nt * 8 + tg * 2;
        const float vs0 = VS[bh * 64 + d0];
        const float vs1 = VS[bh * 64 + d0 + 1];
        const int k = h * 64 + d0;
        const int chunk = k >> 5;
        const int p = (k & 31) >> 1;
        const int off = (p >> 3) * 64 + (p & 3) * 16 + ((p >> 2) & 1) * 4;
        uint32_t hh, ll;
        h2split(O[nt][0] * i0 * vs0, O[nt][1] * i0 * vs1, hh, ll);
        *(uint32_t*)(row0p + chunk * 128 + off) = hh;
        *(uint32_t*)(row0p + chunk * 128 + off + 8) = ll;
        h2split(O[nt][2] * i1 * vs0, O[nt][3] * i1 * vs1, hh, ll);
        *(uint32_t*)(row1p + chunk * 128 + off) = hh;
        *(uint32_t*)(row1p + chunk * 128 + off + 8) = ll;
    }
}

// ---------------------------------------------------------------------------
extern "C" void kernel_launch(void* const* d_in, const int* in_sizes, int n_in,
                              void* d_out, int out_size)
{
    (void)in_sizes; (void)n_in; (void)out_size;
    const float* hs = (const float*)d_in[0];
    const float* wq = (const float*)d_in[1];
    const float* bq = (const float*)d_in[2];
    const float* wk = (const float*)d_in[3];
    const float* bk = (const float*)d_in[4];
    const float* wv = (const float*)d_in[5];
    const float* bv = (const float*)d_in[6];
    const float* wo = (const float*)d_in[7];
    const float* bo = (const float*)d_in[8];
    float* out = (float*)d_out;

    float *q, *k, *v, *s, *vs;
    char *hsi, *wi, *ctxi, *qi, *ki;
    cudaGetSymbolAddress((void**)&q, g_q);
    cudaGetSymbolAddress((void**)&k, g_k);
    cudaGetSymbolAddress((void**)&v, g_v);
    cudaGetSymbolAddress((void**)&s, g_s);
    cudaGetSymbolAddress((void**)&vs, g_vs);
    cudaGetSymbolAddress((void**)&hsi, g_hsi);
    cudaGetSymbolAddress((void**)&wi, g_wi);
    cudaGetSymbolAddress((void**)&ctxi, g_ctxi);
    cudaGetSymbolAddress((void**)&qi, g_qi);
    cudaGetSymbolAddress((void**)&ki, g_ki);

    cudaFuncSetAttribute(tc_gemm<0>, cudaFuncAttributeMaxDynamicSharedMemorySize,
                         GEMM_SMEM_);
    cudaFuncSetAttribute(tc_gemm<1>, cudaFuncAttributeMaxDynamicSharedMemorySize,
                         GEMM_SMEM_);
    cudaFuncSetAttribute(attn_mma, cudaFuncAttributeMaxDynamicSharedMemorySize,
                         ATTN_SMEM_);

    // split hs + 4 weights into hi/lo fp16 fragment images
    split_all<<<(BT_ + 4 * E_) * 512 / 256, 256>>>(hs, wq, wk, wv, wo, hsi, wi);

    dim3 gemmGrid(E_ / 128, BT_ / 128);  // (16, 32)
    const size_t WPITCH = (size_t)E_ * E_ * 4 / 16;

    // QKV projections — separate launches (measured best arrangement)
    tc_gemm<1><<<gemmGrid, 256, GEMM_SMEM_>>>(
        (const uint4*)hsi, (const uint4*)wi, bq, q, 0.125f);
    tc_gemm<1><<<gemmGrid, 256, GEMM_SMEM_>>>(
        (const uint4*)hsi, (const uint4*)wi + WPITCH, bk, k, 1.0f);
    tc_gemm<1><<<gemmGrid, 256, GEMM_SMEM_>>>(
        (const uint4*)hsi, (const uint4*)wi + 2 * WPITCH, bv, v, 1.0f);

    // merged stats (SmoothK absmax + V quant), then merged Q/K image quant
    stats_kernel<<<256, 256>>>(k, v, s, vs);
    row_quant_img_qk<<<2 * BH_ * T_ / 8, 256>>>(q, k, s, qi, ki);

    // fused tensor-core causal attention (reads Q/K images, writes ctx image)
    attn_mma<<<dim3(8, BH_), 256, ATTN_SMEM_>>>(
        (const uint4*)qi, (const uint4*)ki, v, vs, ctxi);

    // output projection (consumes ctx image + wo image)
    tc_gemm<0><<<gemmGrid, 256, GEMM_SMEM_>>>(
        (const uint4*)ctxi, (const uint4*)wi + 3 * WPITCH, bo, out, 1.0f);
}